// round 15
// baseline (speedup 1.0000x reference)
#include <cuda_runtime.h>
#include <math.h>

// Problem constants (fixed by reference)
#define IMG_W 128
#define IMG_H 128
#define TILE  16              // 16x16 tiles -> 8*8*B = 128 blocks (single wave)
#define PIX   256             // pixels per tile
#define SPLIT 16              // gaussian-axis interleave (within-warp subs)
#define NT    1024            // threads per block
#define CHUNK 1024            // gaussians per chunk (1 per thread)
#define NWARP (NT / 32)       // 32

__device__ __forceinline__ float ex2f(float x) {
    float r;
    asm("ex2.approx.f32 %0, %1;" : "=f"(r) : "f"(x));
    return r;
}
__device__ __forceinline__ float lg2f(float x) {
    float r;
    asm("lg2.approx.f32 %0, %1;" : "=f"(r) : "f"(x));
    return r;
}

// Fully fused, pipelined; 4 pixels/thread, warp-internal sub reduction.
__global__ void __launch_bounds__(NT)
fused_kernel(float* __restrict__ out,
             const float* __restrict__ pos,
             const float* __restrict__ col,
             const float* __restrict__ opa,
             const float* __restrict__ sca,
             const float* __restrict__ qv,
             const float* __restrict__ tv,
             int N) {
    __shared__ float4 sP1[CHUNK];     // {projx, projy, K2, lo}
    __shared__ float4 sP2[CHUNK];     // {r, g, b, 1}
    __shared__ int    sWCnt[NWARP];
    __shared__ float  sCam[12];       // folded camera (kept out of registers)

    const int t    = threadIdx.x;
    const int lane = t & 31;
    const int wid  = t >> 5;
    const int sub  = t & (SPLIT - 1);   // 0..15 : gaussian slice (within warp)
    const int quad = t >> 4;            // 0..63 : pixel column-quad
    const int qx   = quad & (TILE - 1); // x within tile
    const int qy   = quad >> 4;         // 0..3 : row group
    const int b    = blockIdx.z;
    const int x0   = blockIdx.x * TILE;
    const int y0   = blockIdx.y * TILE;
    const float xf  = (float)(x0 + qx);
    const float yfb = (float)(y0 + qy);             // rows qy, qy+4, qy+8, qy+12

    const float fx0 = (float)x0, fx1 = (float)(x0 + TILE - 1);
    const float fy0 = (float)y0, fy1 = (float)(y0 + TILE - 1);

    // t0 computes folded camera into shared; others consume (short live ranges).
    if (t == 0) {
        float qw = qv[b * 4 + 0], qx_ = qv[b * 4 + 1], qy_ = qv[b * 4 + 2], qz_ = qv[b * 4 + 3];
        float inv = rsqrtf(qw * qw + qx_ * qx_ + qy_ * qy_ + qz_ * qz_);
        qw *= inv; qx_ *= inv; qy_ *= inv; qz_ *= inv;
        float R00 = 1.f - 2.f * (qy_ * qy_ + qz_ * qz_), R01 = 2.f * (qx_ * qy_ - qz_ * qw), R02 = 2.f * (qx_ * qz_ + qy_ * qw);
        float R10 = 2.f * (qx_ * qy_ + qz_ * qw), R11 = 1.f - 2.f * (qx_ * qx_ + qz_ * qz_), R12 = 2.f * (qy_ * qz_ - qx_ * qw);
        float R20 = 2.f * (qx_ * qz_ - qy_ * qw), R21 = 2.f * (qy_ * qz_ + qx_ * qw), R22 = 1.f - 2.f * (qx_ * qx_ + qy_ * qy_);
        float tx = tv[b * 3 + 0], ty = tv[b * 3 + 1], tz = tv[b * 3 + 2];
        sCam[0] = R20; sCam[1] = R21; sCam[2] = R22; sCam[3] = tz;
        sCam[4] = fmaf(500.f, R00, 64.f * R20); sCam[5]  = fmaf(500.f, R01, 64.f * R21);
        sCam[6] = fmaf(500.f, R02, 64.f * R22); sCam[7]  = fmaf(500.f, tx, 64.f * tz);
        sCam[8] = fmaf(500.f, R10, 64.f * R20); sCam[9]  = fmaf(500.f, R11, 64.f * R21);
        sCam[10] = fmaf(500.f, R12, 64.f * R22); sCam[11] = fmaf(500.f, ty, 64.f * tz);
    }

    float aR[4] = {0.f, 0.f, 0.f, 0.f};
    float aG[4] = {0.f, 0.f, 0.f, 0.f};
    float aB[4] = {0.f, 0.f, 0.f, 0.f};
    float aD[4] = {0.f, 0.f, 0.f, 0.f};

    // ---- Prologue: prefetch chunk 0 pos/sca ----
    float cPx = 0.f, cPy = 0.f, cPz = 0.f, cSc = 1.f;
    if (t < N) {
        cPx = pos[t * 3 + 0]; cPy = pos[t * 3 + 1]; cPz = pos[t * 3 + 2];
        cSc = sca[t];
    }
    __syncthreads();   // sCam visible

    volatile const float* vc = sCam;   // force per-chunk reload (reg relief)

    for (int base = 0; base < N; base += CHUNK) {
        const int g = base + t;
        const bool valid = g < N;

        // ---- Phase 1: project + conservative cull (lo <= 0 bound) ----
        float czm = vc[0] * cPx + vc[1] * cPy + vc[2] * cPz + vc[3];
        float iz  = __fdividef(1.0f, czm);
        float projx = (vc[4] * cPx + vc[5] * cPy + vc[6] * cPz + vc[7])  * iz;
        float projy = (vc[8] * cPx + vc[9] * cPy + vc[10] * cPz + vc[11]) * iz;
        float K2 = __fdividef(-0.72134752044f, cSc * cSc);   // -1/(2 var ln2)

        float dx = fmaxf(0.f, fmaxf(fx0 - projx, projx - fx1));
        float dy = fmaxf(0.f, fmaxf(fy0 - projy, projy - fy1));
        float amax = K2 * fmaf(dx, dx, dy * dy);
        bool keepIt = valid && (amax > -60.f);               // NaN fails -> culled

        // ---- Prefetch next chunk pos/sca ----
        {
            int gn = base + CHUNK + t;
            if (gn < N) {
                cPx = pos[gn * 3 + 0]; cPy = pos[gn * 3 + 1]; cPz = pos[gn * 3 + 2];
                cSc = sca[gn];
            }
        }

        // ---- Phase 2: ballot; counts; barrier doubles as smem-reuse guard ----
        unsigned m = __ballot_sync(0xffffffffu, keepIt);
        int myOff = __popc(m & ((1u << lane) - 1u));
        if (lane == 0) sWCnt[wid] = __popc(m);
        __syncthreads();

        // ---- Phase 3: redundant all-warp scan; survivors fetch opa/col here ----
        int cvec = sWCnt[lane];
        int incl = cvec;
        #pragma unroll
        for (int o = 1; o < 32; o <<= 1) {
            int v = __shfl_up_sync(0xffffffffu, incl, o);
            if (lane >= o) incl += v;
        }
        int warpBase = __shfl_sync(0xffffffffu, incl - cvec, wid);
        int cnt      = __shfl_sync(0xffffffffu, incl, 31);

        if (keepIt) {
            int wpos = warpBase + myOff;
            float lo = lg2f(fmaxf(opa[g], 1e-30f));
            sP1[wpos] = make_float4(projx, projy, K2, lo);
            sP2[wpos] = make_float4(col[g * 3 + 0], col[g * 3 + 1], col[g * 3 + 2], 1.0f);
        }
        __syncthreads();

        // ---- Phase 4: accumulate; 4 pixels share LDS + dx work ----
        #pragma unroll 2
        for (int i = sub; i < cnt; i += SPLIT) {
            float4 p1 = sP1[i];
            float4 p2 = sP2[i];
            float ddx  = xf - p1.x;
            float argx = fmaf(p1.z, ddx * ddx, p1.w);        // K2*dx^2 + lo
            #pragma unroll
            for (int r = 0; r < 4; ++r) {
                float dyr = (yfb + (float)(4 * r)) - p1.y;
                float e   = ex2f(fmaf(p1.z * dyr, dyr, argx));
                aD[r] += e;
                aR[r] = fmaf(e, p2.x, aR[r]);
                aG[r] = fmaf(e, p2.y, aG[r]);
                aB[r] = fmaf(e, p2.z, aB[r]);
            }
        }
        // no trailing sync: next iteration's post-ballot barrier guards reuse
    }

    // ---- Final: butterfly-reduce the 16 subs inside each warp (deterministic:
    // fp add is bitwise-commutative, identical tree on all lanes) ----
    #pragma unroll
    for (int msk = 1; msk < SPLIT; msk <<= 1) {
        #pragma unroll
        for (int r = 0; r < 4; ++r) {
            aR[r] += __shfl_xor_sync(0xffffffffu, aR[r], msk);
            aG[r] += __shfl_xor_sync(0xffffffffu, aG[r], msk);
            aB[r] += __shfl_xor_sync(0xffffffffu, aB[r], msk);
            aD[r] += __shfl_xor_sync(0xffffffffu, aD[r], msk);
        }
    }

    if (sub == 0) {
        int px = x0 + qx;
        #pragma unroll
        for (int r = 0; r < 4; ++r) {
            int py = y0 + qy + 4 * r;
            float invd = 1.0f / (aD[r] + 1e-8f);
            int o = ((b * 3 + 0) * IMG_H + py) * IMG_W + px;
            out[o]                     = aR[r] * invd;
            out[o + IMG_H * IMG_W]     = aG[r] * invd;
            out[o + 2 * IMG_H * IMG_W] = aB[r] * invd;
        }
    }
}

extern "C" void kernel_launch(void* const* d_in, const int* in_sizes, int n_in,
                              void* d_out, int out_size) {
    const float* positions = (const float*)d_in[0];  // (N,3)
    const float* colors    = (const float*)d_in[1];  // (N,3)
    const float* opacities = (const float*)d_in[2];  // (N,1)
    const float* scales    = (const float*)d_in[3];  // (N,1)
    const float* qvec      = (const float*)d_in[4];  // (B,4)
    const float* tvec      = (const float*)d_in[5];  // (B,3)

    int N = in_sizes[0] / 3;
    int B = in_sizes[4] / 4;

    dim3 grid(IMG_W / TILE, IMG_H / TILE, B);
    fused_kernel<<<grid, NT>>>((float*)d_out, positions, colors, opacities,
                               scales, qvec, tvec, N);
}

// round 16
// speedup vs baseline: 1.0063x; 1.0063x over previous
#include <cuda_runtime.h>
#include <math.h>

// Problem constants (fixed by reference)
#define IMG_W 128
#define IMG_H 128
#define TILE  16              // 16x16 tiles -> 8*8*B = 128 blocks (single wave)
#define PIX   256             // pixels per tile
#define SPLIT 16              // gaussian-axis interleave (sub = t>>6, warp-constant)
#define NT    1024            // threads per block
#define CHUNK 1024            // gaussians per chunk (1 per thread)
#define NWARP (NT / 32)       // 32

__device__ __forceinline__ float ex2f(float x) {
    float r;
    asm("ex2.approx.f32 %0, %1;" : "=f"(r) : "f"(x));
    return r;
}
__device__ __forceinline__ float lg2f(float x) {
    float r;
    asm("lg2.approx.f32 %0, %1;" : "=f"(r) : "f"(x));
    return r;
}

// Fully fused, pipelined; 4 pixels/thread, warp-constant sub (broadcast LDS).
__global__ void __launch_bounds__(NT)
fused_kernel(float* __restrict__ out,
             const float* __restrict__ pos,
             const float* __restrict__ col,
             const float* __restrict__ opa,
             const float* __restrict__ sca,
             const float* __restrict__ qv,
             const float* __restrict__ tv,
             int N) {
    // Survivor tables during chunks; reused as the 8x256 partial table at the end.
    __shared__ float4 sBuf[2 * CHUNK];          // 32 KB
    __shared__ int    sWCnt[NWARP];
    __shared__ float  sCam[12];
    float4* sP1 = sBuf;                         // {projx, projy, K2, lo}
    float4* sP2 = sBuf + CHUNK;                 // {r, g, b, 1}

    const int t    = threadIdx.x;
    const int lane = t & 31;
    const int wid  = t >> 5;
    const int sub  = t >> 6;            // 0..15 : gaussian slice (warp-constant!)
    const int slot = t & 63;            // pixel slot
    const int qx   = slot & (TILE - 1); // x within tile
    const int qy   = slot >> 4;         // 0..3 : row group (rows qy+4r)
    const int b    = blockIdx.z;
    const int x0   = blockIdx.x * TILE;
    const int y0   = blockIdx.y * TILE;
    const float xf  = (float)(x0 + qx);
    const float yfb = (float)(y0 + qy);

    const float fx0 = (float)x0, fx1 = (float)(x0 + TILE - 1);
    const float fy0 = (float)y0, fy1 = (float)(y0 + TILE - 1);

    // t0 computes folded camera into shared (keeps invariants out of registers).
    if (t == 0) {
        float qw = qv[b * 4 + 0], qx_ = qv[b * 4 + 1], qy_ = qv[b * 4 + 2], qz_ = qv[b * 4 + 3];
        float inv = rsqrtf(qw * qw + qx_ * qx_ + qy_ * qy_ + qz_ * qz_);
        qw *= inv; qx_ *= inv; qy_ *= inv; qz_ *= inv;
        float R00 = 1.f - 2.f * (qy_ * qy_ + qz_ * qz_), R01 = 2.f * (qx_ * qy_ - qz_ * qw), R02 = 2.f * (qx_ * qz_ + qy_ * qw);
        float R10 = 2.f * (qx_ * qy_ + qz_ * qw), R11 = 1.f - 2.f * (qx_ * qx_ + qz_ * qz_), R12 = 2.f * (qy_ * qz_ - qx_ * qw);
        float R20 = 2.f * (qx_ * qz_ - qy_ * qw), R21 = 2.f * (qy_ * qz_ + qx_ * qw), R22 = 1.f - 2.f * (qx_ * qx_ + qy_ * qy_);
        float tx = tv[b * 3 + 0], ty = tv[b * 3 + 1], tz = tv[b * 3 + 2];
        sCam[0] = R20; sCam[1] = R21; sCam[2] = R22; sCam[3] = tz;
        sCam[4] = fmaf(500.f, R00, 64.f * R20); sCam[5]  = fmaf(500.f, R01, 64.f * R21);
        sCam[6] = fmaf(500.f, R02, 64.f * R22); sCam[7]  = fmaf(500.f, tx, 64.f * tz);
        sCam[8] = fmaf(500.f, R10, 64.f * R20); sCam[9]  = fmaf(500.f, R11, 64.f * R21);
        sCam[10] = fmaf(500.f, R12, 64.f * R22); sCam[11] = fmaf(500.f, ty, 64.f * tz);
    }

    float aR[4] = {0.f, 0.f, 0.f, 0.f};
    float aG[4] = {0.f, 0.f, 0.f, 0.f};
    float aB[4] = {0.f, 0.f, 0.f, 0.f};
    float aD[4] = {0.f, 0.f, 0.f, 0.f};

    // ---- Prologue: prefetch chunk 0 pos/sca ----
    float cPx = 0.f, cPy = 0.f, cPz = 0.f, cSc = 1.f;
    if (t < N) {
        cPx = pos[t * 3 + 0]; cPy = pos[t * 3 + 1]; cPz = pos[t * 3 + 2];
        cSc = sca[t];
    }
    __syncthreads();   // sCam visible

    volatile const float* vc = sCam;   // reload per chunk (register relief)

    for (int base = 0; base < N; base += CHUNK) {
        const int g = base + t;
        const bool valid = g < N;

        // ---- Phase 1: project + conservative cull (lo <= 0 bound) ----
        float czm = vc[0] * cPx + vc[1] * cPy + vc[2] * cPz + vc[3];
        float iz  = __fdividef(1.0f, czm);
        float projx = (vc[4] * cPx + vc[5] * cPy + vc[6] * cPz + vc[7])  * iz;
        float projy = (vc[8] * cPx + vc[9] * cPy + vc[10] * cPz + vc[11]) * iz;
        float K2 = __fdividef(-0.72134752044f, cSc * cSc);   // -1/(2 var ln2)

        float dx = fmaxf(0.f, fmaxf(fx0 - projx, projx - fx1));
        float dy = fmaxf(0.f, fmaxf(fy0 - projy, projy - fy1));
        float amax = K2 * fmaf(dx, dx, dy * dy);
        bool keepIt = valid && (amax > -60.f);               // NaN fails -> culled

        // ---- Prefetch next chunk pos/sca ----
        {
            int gn = base + CHUNK + t;
            if (gn < N) {
                cPx = pos[gn * 3 + 0]; cPy = pos[gn * 3 + 1]; cPz = pos[gn * 3 + 2];
                cSc = sca[gn];
            }
        }

        // ---- Phase 2: ballot; counts; barrier doubles as smem-reuse guard ----
        unsigned m = __ballot_sync(0xffffffffu, keepIt);
        int myOff = __popc(m & ((1u << lane) - 1u));
        if (lane == 0) sWCnt[wid] = __popc(m);
        __syncthreads();

        // ---- Phase 3: redundant all-warp scan; survivors fetch opa/col here ----
        int cvec = sWCnt[lane];
        int incl = cvec;
        #pragma unroll
        for (int o = 1; o < 32; o <<= 1) {
            int v = __shfl_up_sync(0xffffffffu, incl, o);
            if (lane >= o) incl += v;
        }
        int warpBase = __shfl_sync(0xffffffffu, incl - cvec, wid);
        int cnt      = __shfl_sync(0xffffffffu, incl, 31);

        if (keepIt) {
            int wpos = warpBase + myOff;
            float lo = lg2f(fmaxf(opa[g], 1e-30f));
            sP1[wpos] = make_float4(projx, projy, K2, lo);
            sP2[wpos] = make_float4(col[g * 3 + 0], col[g * 3 + 1], col[g * 3 + 2], 1.0f);
        }
        __syncthreads();

        // ---- Phase 4: accumulate; 4 pixels share broadcast LDS + dx work ----
        #pragma unroll 2
        for (int i = sub; i < cnt; i += SPLIT) {
            float4 p1 = sP1[i];      // same address across warp -> broadcast
            float4 p2 = sP2[i];
            float ddx  = xf - p1.x;
            float argx = fmaf(p1.z, ddx * ddx, p1.w);        // K2*dx^2 + lo
            #pragma unroll
            for (int r = 0; r < 4; ++r) {
                float dyr = (yfb + (float)(4 * r)) - p1.y;
                float e   = ex2f(fmaf(p1.z * dyr, dyr, argx));
                aD[r] += e;
                aR[r] = fmaf(e, p2.x, aR[r]);
                aG[r] = fmaf(e, p2.y, aG[r]);
                aB[r] = fmaf(e, p2.z, aB[r]);
            }
        }
        // no trailing sync: next iteration's post-ballot barrier guards reuse
    }

    // ---- Final combine: 16 subs -> 8 partials (paired add) -> fold ----
    __syncthreads();
    float4* sAcc = sBuf;    // 2048 entries = 8 subs x 256 pixels
    if (sub < 8) {
        #pragma unroll
        for (int r = 0; r < 4; ++r) {
            int pix = (qy + 4 * r) * TILE + qx;
            sAcc[sub * PIX + pix] = make_float4(aR[r], aG[r], aB[r], aD[r]);
        }
    }
    __syncthreads();
    if (sub >= 8) {
        #pragma unroll
        for (int r = 0; r < 4; ++r) {
            int pix = (qy + 4 * r) * TILE + qx;
            float4 a = sAcc[(sub - 8) * PIX + pix];
            a.x += aR[r]; a.y += aG[r]; a.z += aB[r]; a.w += aD[r];
            sAcc[(sub - 8) * PIX + pix] = a;
        }
    }
    __syncthreads();

    if (t < PIX) {
        float r = 0.f, g = 0.f, bl = 0.f, d = 0.f;
        #pragma unroll
        for (int s = 0; s < 8; ++s) {
            float4 a = sAcc[s * PIX + t];
            r += a.x; g += a.y; bl += a.z; d += a.w;
        }
        float invd = 1.0f / (d + 1e-8f);
        int px = x0 + (t & (TILE - 1));
        int py = y0 + (t >> 4);
        int o = ((b * 3 + 0) * IMG_H + py) * IMG_W + px;
        out[o]                     = r  * invd;
        out[o + IMG_H * IMG_W]     = g  * invd;
        out[o + 2 * IMG_H * IMG_W] = bl * invd;
    }
}

extern "C" void kernel_launch(void* const* d_in, const int* in_sizes, int n_in,
                              void* d_out, int out_size) {
    const float* positions = (const float*)d_in[0];  // (N,3)
    const float* colors    = (const float*)d_in[1];  // (N,3)
    const float* opacities = (const float*)d_in[2];  // (N,1)
    const float* scales    = (const float*)d_in[3];  // (N,1)
    const float* qvec      = (const float*)d_in[4];  // (B,4)
    const float* tvec      = (const float*)d_in[5];  // (B,3)

    int N = in_sizes[0] / 3;
    int B = in_sizes[4] / 4;

    dim3 grid(IMG_W / TILE, IMG_H / TILE, B);
    fused_kernel<<<grid, NT>>>((float*)d_out, positions, colors, opacities,
                               scales, qvec, tvec, N);
}

// round 17
// speedup vs baseline: 1.0523x; 1.0458x over previous
#include <cuda_runtime.h>
#include <math.h>

// Problem constants (fixed by reference)
#define IMG_W 128
#define IMG_H 128
#define TILE  16              // 16x16 tiles -> 8*8*B = 128 blocks (single wave)
#define PIX   256             // pixels per tile
#define HALF  128             // pixel-pairs per tile (each thread: rows y, y+8)
#define SPLIT 8               // gaussian-axis interleave (sub = t>>7, warp-constant)
#define NT    1024            // threads per block
#define CHUNK 1024            // gaussians per chunk (1 per thread)
#define NWARP (NT / 32)       // 32
#define GRP   96              // survivors per separable-table group (12 KB table)

__device__ __forceinline__ float ex2f(float x) {
    float r;
    asm("ex2.approx.f32 %0, %1;" : "=f"(r) : "f"(x));
    return r;
}
__device__ __forceinline__ float lg2f(float x) {
    float r;
    asm("lg2.approx.f32 %0, %1;" : "=f"(r) : "f"(x));
    return r;
}

// Fused + pipelined + separable accumulate: per survivor-group, build
// Ex/Ey tables (32 exp2 per survivor) then a MUFU-free inner loop.
__global__ void __launch_bounds__(NT)
fused_kernel(float* __restrict__ out,
             const float* __restrict__ pos,
             const float* __restrict__ col,
             const float* __restrict__ opa,
             const float* __restrict__ sca,
             const float* __restrict__ qv,
             const float* __restrict__ tv,
             int N) {
    __shared__ float4 sBuf[2 * CHUNK];   // sP1 | sP2 ; reused as sAcc at the end
    __shared__ float  sT[GRP * 32];      // per-group: [il][0:16)=Ex, [16:32)=Ey
    __shared__ int    sWCnt[NWARP];
    float4* sP1 = sBuf;                  // {projx, projy, K2, lo}
    float4* sP2 = sBuf + CHUNK;          // {r, g, b, 1}

    const int t    = threadIdx.x;
    const int lane = t & 31;
    const int wid  = t >> 5;
    const int sub  = t >> 7;             // 0..7 : survivor slice (warp-constant)
    const int half = t & (HALF - 1);     // pixel-pair id 0..127
    const int xi   = half & (TILE - 1);  // x in tile
    const int yiA  = half >> 4;          // rows 0..7 ; B = +8
    const int b    = blockIdx.z;
    const int x0   = blockIdx.x * TILE;
    const int y0   = blockIdx.y * TILE;

    const float fx0 = (float)x0, fx1 = (float)(x0 + TILE - 1);
    const float fy0 = (float)y0, fy1 = (float)(y0 + TILE - 1);

    // Camera; fold projection constants: proj = (A·p + At) / (R2·p + tz)
    float qw = qv[b * 4 + 0], qx = qv[b * 4 + 1], qy = qv[b * 4 + 2], qz = qv[b * 4 + 3];
    float inv = rsqrtf(qw * qw + qx * qx + qy * qy + qz * qz);
    qw *= inv; qx *= inv; qy *= inv; qz *= inv;
    const float R00 = 1.f - 2.f * (qy * qy + qz * qz), R01 = 2.f * (qx * qy - qz * qw), R02 = 2.f * (qx * qz + qy * qw);
    const float R10 = 2.f * (qx * qy + qz * qw), R11 = 1.f - 2.f * (qx * qx + qz * qz), R12 = 2.f * (qy * qz - qx * qw);
    const float R20 = 2.f * (qx * qz - qy * qw), R21 = 2.f * (qy * qz + qx * qw), R22 = 1.f - 2.f * (qx * qx + qy * qy);
    const float tx = tv[b * 3 + 0], ty = tv[b * 3 + 1], tz = tv[b * 3 + 2];
    const float A00 = fmaf(500.f, R00, 64.f * R20), A01 = fmaf(500.f, R01, 64.f * R21), A02 = fmaf(500.f, R02, 64.f * R22);
    const float A10 = fmaf(500.f, R10, 64.f * R20), A11 = fmaf(500.f, R11, 64.f * R21), A12 = fmaf(500.f, R12, 64.f * R22);
    const float Atx = fmaf(500.f, tx, 64.f * tz),   Aty = fmaf(500.f, ty, 64.f * tz);

    float aRA = 0.f, aGA = 0.f, aBA = 0.f, aDA = 0.f;
    float aRB = 0.f, aGB = 0.f, aBB = 0.f, aDB = 0.f;

    // ---- Prologue: prefetch chunk 0 pos/sca ----
    float cPx = 0.f, cPy = 0.f, cPz = 0.f, cSc = 1.f;
    if (t < N) {
        cPx = pos[t * 3 + 0]; cPy = pos[t * 3 + 1]; cPz = pos[t * 3 + 2];
        cSc = sca[t];
    }

    for (int base = 0; base < N; base += CHUNK) {
        const int g = base + t;
        const bool valid = g < N;

        // ---- Phase 1: project + conservative cull (lo <= 0 bound) ----
        float czm = R20 * cPx + R21 * cPy + R22 * cPz + tz;
        float iz  = __fdividef(1.0f, czm);
        float projx = (A00 * cPx + A01 * cPy + A02 * cPz + Atx) * iz;
        float projy = (A10 * cPx + A11 * cPy + A12 * cPz + Aty) * iz;
        float K2 = __fdividef(-0.72134752044f, cSc * cSc);   // -1/(2 var ln2)

        float dx = fmaxf(0.f, fmaxf(fx0 - projx, projx - fx1));
        float dy = fmaxf(0.f, fmaxf(fy0 - projy, projy - fy1));
        float amax = K2 * fmaf(dx, dx, dy * dy);
        bool keepIt = valid && (amax > -60.f);               // NaN fails -> culled

        // ---- Prefetch next chunk pos/sca (drains behind everything below) ----
        {
            int gn = base + CHUNK + t;
            if (gn < N) {
                cPx = pos[gn * 3 + 0]; cPy = pos[gn * 3 + 1]; cPz = pos[gn * 3 + 2];
                cSc = sca[gn];
            }
        }

        // ---- Phase 2: ballot; counts; barrier doubles as smem-reuse guard ----
        unsigned m = __ballot_sync(0xffffffffu, keepIt);
        int myOff = __popc(m & ((1u << lane) - 1u));
        if (lane == 0) sWCnt[wid] = __popc(m);
        __syncthreads();

        // ---- Phase 3: redundant all-warp scan; survivors fetch opa/col here ----
        int cvec = sWCnt[lane];
        int incl = cvec;
        #pragma unroll
        for (int o = 1; o < 32; o <<= 1) {
            int v = __shfl_up_sync(0xffffffffu, incl, o);
            if (lane >= o) incl += v;
        }
        int warpBase = __shfl_sync(0xffffffffu, incl - cvec, wid);
        int cnt      = __shfl_sync(0xffffffffu, incl, 31);

        if (keepIt) {
            int wpos = warpBase + myOff;
            float lo = lg2f(fmaxf(opa[g], 1e-30f));
            sP1[wpos] = make_float4(projx, projy, K2, lo);
            sP2[wpos] = make_float4(col[g * 3 + 0], col[g * 3 + 1], col[g * 3 + 2], 1.0f);
        }
        __syncthreads();

        // ---- Phase 4: per survivor-group: build Ex/Ey tables, then MUFU-free
        //      accumulate. 32 exp2 per survivor instead of 256. ----
        for (int g0 = 0; g0 < cnt; g0 += GRP) {
            int gc = min(GRP, cnt - g0);

            // Build: gc*32 values; each warp handles one survivor per pass.
            #pragma unroll
            for (int it = 0; it < 3; ++it) {
                int v = t + it * NT;
                if (v < gc * 32) {
                    int il = v >> 5;
                    int j  = v & 31;
                    float4 p1 = sP1[g0 + il];        // broadcast within warp
                    float val;
                    if (j < 16) {
                        float d = (fx0 + (float)j) - p1.x;
                        val = ex2f(fmaf(p1.z * d, d, p1.w));   // Ex (lo folded)
                    } else {
                        float d = (fy0 + (float)(j - 16)) - p1.y;
                        val = ex2f(p1.z * d * d);              // Ey
                    }
                    sT[il * 32 + j] = val;
                }
            }
            __syncthreads();

            // Accumulate: e = Ex[x] * Ey[y]; 2 pixels share Ex + colors.
            #pragma unroll 2
            for (int il = sub; il < gc; il += SPLIT) {
                const float* row = sT + il * 32;
                float Ex  = row[xi];
                float EyA = row[16 + yiA];
                float EyB = row[24 + yiA];           // yiB = yiA + 8
                float4 c  = sP2[g0 + il];            // broadcast LDS.128
                float eA = Ex * EyA;
                float eB = Ex * EyB;
                aDA += eA;
                aRA = fmaf(eA, c.x, aRA);
                aGA = fmaf(eA, c.y, aGA);
                aBA = fmaf(eA, c.z, aBA);
                aDB += eB;
                aRB = fmaf(eB, c.x, aRB);
                aGB = fmaf(eB, c.y, aGB);
                aBB = fmaf(eB, c.z, aBB);
            }
            if (g0 + GRP < cnt) __syncthreads();     // sT reuse guard (same chunk)
        }
        // next chunk's post-ballot barrier guards sP/sT reuse across chunks
    }

    // ---- Final: 8-sub fixed-order combine via reused shared ----
    __syncthreads();
    float4* sAcc = sBuf;                 // 2048 entries: [sub][pixel]
    sAcc[sub * PIX + half]        = make_float4(aRA, aGA, aBA, aDA);
    sAcc[sub * PIX + half + HALF] = make_float4(aRB, aGB, aBB, aDB);
    __syncthreads();

    if (t < PIX) {
        float r = 0.f, g = 0.f, bl = 0.f, d = 0.f;
        #pragma unroll
        for (int s = 0; s < SPLIT; ++s) {
            float4 a = sAcc[s * PIX + t];
            r += a.x; g += a.y; bl += a.z; d += a.w;
        }
        float invd = 1.0f / (d + 1e-8f);
        int px = x0 + (t & (TILE - 1));
        int py = y0 + (t >> 4);
        int o = ((b * 3 + 0) * IMG_H + py) * IMG_W + px;
        out[o]                     = r  * invd;
        out[o + IMG_H * IMG_W]     = g  * invd;
        out[o + 2 * IMG_H * IMG_W] = bl * invd;
    }
}

extern "C" void kernel_launch(void* const* d_in, const int* in_sizes, int n_in,
                              void* d_out, int out_size) {
    const float* positions = (const float*)d_in[0];  // (N,3)
    const float* colors    = (const float*)d_in[1];  // (N,3)
    const float* opacities = (const float*)d_in[2];  // (N,1)
    const float* scales    = (const float*)d_in[3];  // (N,1)
    const float* qvec      = (const float*)d_in[4];  // (B,4)
    const float* tvec      = (const float*)d_in[5];  // (B,3)

    int N = in_sizes[0] / 3;
    int B = in_sizes[4] / 4;

    dim3 grid(IMG_W / TILE, IMG_H / TILE, B);
    fused_kernel<<<grid, NT>>>((float*)d_out, positions, colors, opacities,
                               scales, qvec, tvec, N);
}